// round 7
// baseline (speedup 1.0000x reference)
#include <cuda_runtime.h>

#define T_STEPS 512
#define IN_F 5
#define HDIM 7
#define TS 64
#define NTILE (T_STEPS / TS)
#define XROW (TS * IN_F + 12)   // 332 words
#define OROW (TS * 4 + 4)       // 260 words

typedef unsigned long long u64;

__device__ __forceinline__ float tanh_ap(float a) {
    float r; asm("tanh.approx.f32 %0, %1;" : "=f"(r) : "f"(a)); return r;
}
__device__ __forceinline__ u64 pk(float lo, float hi) {
    u64 r; asm("mov.b64 %0, {%1, %2};" : "=l"(r) : "f"(lo), "f"(hi)); return r;
}
__device__ __forceinline__ u64 pk1(float v) { return pk(v, v); }
__device__ __forceinline__ void up(u64 v, float& lo, float& hi) {
    asm("mov.b64 {%0, %1}, %2;" : "=f"(lo), "=f"(hi) : "l"(v));
}
__device__ __forceinline__ u64 f2(u64 a, u64 b, u64 c) {
    u64 d; asm("fma.rn.f32x2 %0, %1, %2, %3;" : "=l"(d) : "l"(a), "l"(b), "l"(c)); return d;
}
__device__ __forceinline__ u64 a2(u64 a, u64 b) {
    u64 d; asm("add.rn.f32x2 %0, %1, %2;" : "=l"(d) : "l"(a), "l"(b)); return d;
}

// 1 warp/CTA; warp = 4 batches x 8 lanes. Lane L owns hidden unit L (unit 7 dummy).
// r|z gates packed (pre-halved weights); n-gate packed with the output head dot.
__global__ void __launch_bounds__(32) gru_kernel(
    const float* __restrict__ x,
    const float* __restrict__ W_ih, const float* __restrict__ W_hh,
    const float* __restrict__ b_ih, const float* __restrict__ b_hh,
    const float* __restrict__ W_h0,
    const float* __restrict__ W_m, const float* __restrict__ b_m,
    const float* __restrict__ W_r, const float* __restrict__ b_r,
    float* __restrict__ out, int B)
{
    __shared__ float xs[4 * XROW];
    __shared__ float os[4 * OROW];

    int lane = threadIdx.x;
    int g = lane >> 3;          // batch slot within warp
    int L = lane & 7;           // hidden unit
    int hd = L & 3;             // head row for this lane (L<4 stores)
    int b = blockIdx.x * 4 + g;

    float* out_m = out;                             // [B, T, 3]
    float* out_r = out + (size_t)B * T_STEPS * 3;   // [B, T, 1]
    float* out_h = out + (size_t)B * T_STEPS * 4;   // [1, B, H]

    // ---- packed per-lane weights ----
    u64 pwh_rz[HDIM], pwh_nh[HDIM], pwi_rz[IN_F];
    u64 pb_rz, pbn_h;
    float win_[IN_F], bxn, h;
    {
        bool v = (L < HDIM);
        int ur = L, uz = HDIM + L, un = 2 * HDIM + L;
#pragma unroll
        for (int k = 0; k < HDIM; k++) {
            float wr = v ? 0.5f * W_hh[ur * HDIM + k] : 0.f;
            float wz = v ? 0.5f * W_hh[uz * HDIM + k] : 0.f;
            pwh_rz[k] = pk(wr, wz);
            float wn = v ? W_hh[un * HDIM + k] : 0.f;
            float wh = (hd < 3) ? W_m[hd * HDIM + k] : W_r[k];
            pwh_nh[k] = pk(wn, wh);
        }
#pragma unroll
        for (int i = 0; i < IN_F; i++) {
            float wr = v ? 0.5f * W_ih[ur * IN_F + i] : 0.f;
            float wz = v ? 0.5f * W_ih[uz * IN_F + i] : 0.f;
            pwi_rz[i] = pk(wr, wz);
            win_[i] = v ? W_ih[un * IN_F + i] : 0.f;
        }
        pb_rz = pk(v ? 0.5f * (b_ih[ur] + b_hh[ur]) : 0.f,
                   v ? 0.5f * (b_ih[uz] + b_hh[uz]) : 0.f);
        float ob = (hd < 3) ? b_m[hd] : b_r[0];
        pbn_h = pk(v ? b_hh[un] : 0.f, ob);
        bxn = v ? b_ih[un] : 0.f;
        h = v ? W_h0[L] : 0.f;
    }

    const float* xb = x + (size_t)b * T_STEPS * IN_F;
    float* xrow = xs + g * XROW;
    float* orow = os + g * OROW;

    float hall[HDIM];
#pragma unroll
    for (int k = 0; k < HDIM; k++) hall[k] = __shfl_sync(0xffffffffu, h, k, 8);

    for (int tile = 0; tile < NTILE; tile++) {
        int t0 = tile * TS;

        // ---- stage x tile: 4 batches x 320 floats, 10 float4 per lane ----
        __syncwarp();
        const float4* src = (const float4*)(xb + t0 * IN_F);
#pragma unroll
        for (int j = 0; j < 10; j++) {
            float4 v = src[L + 8 * j];
            *(float4*)(xrow + (L + 8 * j) * 4) = v;
        }
        __syncwarp();

        // ---- preamble: projection of x[t0] ----
        u64 prz;
        float xan;
        {
            u64 P = pb_rz; float Xn = bxn;
#pragma unroll
            for (int i = 0; i < IN_F; i++) {
                float xi = xrow[i];
                P = f2(pwi_rz[i], pk1(xi), P);
                Xn = fmaf(win_[i], xi, Xn);
            }
            prz = P; xan = Xn;
        }

#pragma unroll 2
        for (int tt = 0; tt < TS; tt++) {
            // load x for next step's projection
            int t1 = (tt + 1 < TS) ? (tt + 1) : (TS - 1);
            float xv[IN_F];
#pragma unroll
            for (int i = 0; i < IN_F; i++) xv[i] = xrow[t1 * IN_F + i];

            // ---- packed dots over hall(t-1): r|z and n|head ----
            u64 ph[HDIM];
#pragma unroll
            for (int k = 0; k < HDIM; k++) ph[k] = pk1(hall[k]);

            u64 A0 = prz, A1 = 0ULL, N0 = pbn_h, N1 = 0ULL;
#pragma unroll
            for (int k = 0; k < HDIM; k += 2) {
                A0 = f2(pwh_rz[k], ph[k], A0);
                N0 = f2(pwh_nh[k], ph[k], N0);
                if (k + 1 < HDIM) {
                    A1 = f2(pwh_rz[k + 1], ph[k + 1], A1);
                    N1 = f2(pwh_nh[k + 1], ph[k + 1], N1);
                }
            }
            float ar, az, An, hv;
            up(a2(A0, A1), ar, az);
            up(a2(N0, N1), An, hv);

            // head value hv is for step tt-1 (uses hall(t-1)); slot 63 garbage at
            // tt==0 is overwritten by the per-tile epilogue.
            if (L < 4) orow[((tt + TS - 1) % TS) * 4 + hd] = hv;

            // ---- gates (r eliminated: n_arg = c + tanh(Ar')*d) ----
            float tr = tanh_ap(ar);
            float tz = tanh_ap(az);
            float c = fmaf(0.5f, An, xan);
            float d = 0.5f * An;
            float n = tanh_ap(fmaf(tr, d, c));
            float z = fmaf(0.5f, tz, 0.5f);
            h = fmaf(z, h - n, n);

            // gather h(t)
#pragma unroll
            for (int k = 0; k < HDIM; k++)
                hall[k] = __shfl_sync(0xffffffffu, h, k, 8);

            // projection for step t+1 (off critical path)
            u64 P = pb_rz; float Xn = bxn;
#pragma unroll
            for (int i = 0; i < IN_F; i++) {
                P = f2(pwi_rz[i], pk1(xv[i]), P);
                Xn = fmaf(win_[i], xv[i], Xn);
            }
            prz = P; xan = Xn;
        }

        // ---- epilogue: head for step TS-1 from hall = h(TS-1) ----
        {
            float dlo, ob2; up(pbn_h, dlo, ob2);
            float val = ob2;
#pragma unroll
            for (int k = 0; k < HDIM; k++) {
                float wlo, whi; up(pwh_nh[k], wlo, whi);
                val = fmaf(whi, hall[k], val);
            }
            if (L < 4) orow[(TS - 1) * 4 + hd] = val;
        }
        __syncwarp();

        // ---- flush out_m tile: 48 float4/batch, 6 per lane ----
        float* omg = out_m + (size_t)b * T_STEPS * 3 + t0 * 3;
#pragma unroll
        for (int q = 0; q < 6; q++) {
            int p = (8 * q + L) * 4;
            float4 v;
            v.x = orow[((p + 0) / 3) * 4 + (p + 0) % 3];
            v.y = orow[((p + 1) / 3) * 4 + (p + 1) % 3];
            v.z = orow[((p + 2) / 3) * 4 + (p + 2) % 3];
            v.w = orow[((p + 3) / 3) * 4 + (p + 3) % 3];
            *(float4*)(omg + p) = v;
        }
        // ---- flush out_r tile: 16 float4/batch, 2 per lane ----
        float* org = out_r + (size_t)b * T_STEPS + t0;
#pragma unroll
        for (int q = 0; q < 2; q++) {
            int p = (8 * q + L) * 4;
            float4 v;
            v.x = orow[(p + 0) * 4 + 3];
            v.y = orow[(p + 1) * 4 + 3];
            v.z = orow[(p + 2) * 4 + 3];
            v.w = orow[(p + 3) * 4 + 3];
            *(float4*)(org + p) = v;
        }
    }

    if (L < HDIM) out_h[(size_t)b * HDIM + L] = h;
}

extern "C" void kernel_launch(void* const* d_in, const int* in_sizes, int n_in,
                              void* d_out, int out_size) {
    const float* x    = (const float*)d_in[0];
    const float* W_ih = (const float*)d_in[2];
    const float* W_hh = (const float*)d_in[3];
    const float* b_ih = (const float*)d_in[4];
    const float* b_hh = (const float*)d_in[5];
    const float* W_h0 = (const float*)d_in[6];
    const float* W_m  = (const float*)d_in[7];
    const float* b_m  = (const float*)d_in[8];
    const float* W_r  = (const float*)d_in[9];
    const float* b_r  = (const float*)d_in[10];

    int B = in_sizes[0] / (T_STEPS * IN_F);   // 8192
    int grid = (B + 3) / 4;                   // 4 batches per 1-warp CTA
    gru_kernel<<<grid, 32>>>(x, W_ih, W_hh, b_ih, b_hh, W_h0,
                             W_m, b_m, W_r, b_r, (float*)d_out, B);
}